// round 14
// baseline (speedup 1.0000x reference)
#include <cuda_runtime.h>
#include <cuda_fp16.h>
#include <stdint.h>
#include <math.h>

#define BATCH  65536
#define D_DIM  256
#define W_DIM  1024
#define MTILE  64
#define NTHREADS 512
#define CW     128
#define NCHUNK (W_DIM / CW)    // 8
#define NGRID  (BATCH / MTILE) // 1024
#define WSCALE 64.0f
#define WINV   (1.0f / 64.0f)

// device scratch: weights scaled fp16 (z converted in-kernel)
__device__ __align__(16) __half g_w1s[W_DIM * D_DIM];   // W1 * 64
__device__ __align__(16) __half g_w2s[D_DIM * W_DIM];   // W2 * 64
__device__ float g_M[W_DIM];

// ---------------- SMEM layout (bytes), XOR-swizzled, pad-free ----------------
// z  : [64][512B]   (256 fp16/row)
// W1 : [128][512B]  chunk rows = W-col j
// W2 : [256][256B]  chunk (128 fp16/row)
// h  : [64][256B]
#define Z_S    0
#define W1_S   32768
#define W2_S   98304
#define H_S    163840
#define TR_OFF 180224
#define S_TOTAL 180480

// ---------------- PTX helpers ----------------
__device__ __forceinline__ uint32_t smem_u32(const void* p) {
    uint32_t a;
    asm("{ .reg .u64 t; cvta.to.shared.u64 t, %1; cvt.u32.u64 %0, t; }" : "=r"(a) : "l"(p));
    return a;
}
#define CP_ASYNC16(d, s) \
    asm volatile("cp.async.cg.shared.global [%0], [%1], 16;" :: "r"(d), "l"(s))
#define CP_COMMIT() asm volatile("cp.async.commit_group;")
#define CP_WAIT0()  asm volatile("cp.async.wait_group 0;")
#define CP_WAIT1()  asm volatile("cp.async.wait_group 1;")

#define LDSM4(r, addr) \
    asm volatile("ldmatrix.sync.aligned.m8n8.x4.shared.b16 {%0,%1,%2,%3}, [%4];" \
        : "=r"((r)[0]), "=r"((r)[1]), "=r"((r)[2]), "=r"((r)[3]) : "r"(addr))

__device__ __forceinline__ void mma_f16(float* c, const uint32_t* a, uint32_t b0, uint32_t b1) {
    asm volatile(
        "mma.sync.aligned.m16n8k16.row.col.f32.f16.f16.f32 "
        "{%0,%1,%2,%3}, {%4,%5,%6,%7}, {%8,%9}, {%0,%1,%2,%3};"
        : "+f"(c[0]), "+f"(c[1]), "+f"(c[2]), "+f"(c[3])
        : "r"(a[0]), "r"(a[1]), "r"(a[2]), "r"(a[3]), "r"(b0), "r"(b1));
}

// ---------------- fused prepass: weights conv + M, ONE launch ----------------
#define WCONV_BLOCKS 256
union PackH8 { uint4 u; __half h[8]; };

__global__ void prep_kernel(const float* __restrict__ W1,
                            const float* __restrict__ W2) {
    if (blockIdx.x < WCONV_BLOCKS) {
        size_t gid = (size_t)blockIdx.x * 256 + threadIdx.x;
        const float* src;
        __half* dst;
        size_t idx;
        if (gid < 32768) { src = W1; dst = g_w1s; idx = gid; }
        else             { src = W2; dst = g_w2s; idx = gid - 32768; }
        const float4* s = reinterpret_cast<const float4*>(src);
        float4 a = s[idx * 2], b = s[idx * 2 + 1];
        float v[8] = {a.x, a.y, a.z, a.w, b.x, b.y, b.z, b.w};
        PackH8 o;
        #pragma unroll
        for (int i = 0; i < 8; i++) o.h[i] = __float2half_rn(v[i] * WSCALE);
        reinterpret_cast<uint4*>(dst)[idx] = o.u;
    } else {
        int j = blockIdx.x - WCONV_BLOCKS, i = threadIdx.x;
        float v = W1[j * D_DIM + i] * W2[(size_t)i * W_DIM + j];
        #pragma unroll
        for (int o = 16; o > 0; o >>= 1) v += __shfl_down_sync(0xffffffffu, v, o);
        __shared__ float red[8];
        if ((i & 31) == 0) red[i >> 5] = v;
        __syncthreads();
        if (i < 8) {
            float s = red[i];
            #pragma unroll
            for (int o = 4; o > 0; o >>= 1) s += __shfl_down_sync(0xffu, s, o);
            if (i == 0) g_M[j] = s;
        }
    }
}

// ---------------- copy helpers (cp.async, 512 threads, swizzled dst) ---------
// nrows x 256 fp16 (512B rows)
__device__ __forceinline__ void cp_tile512(uint32_t sdst, const __half* g, int nrows) {
    const int total = nrows * 32;
    for (int i = threadIdx.x; i < total; i += NTHREADS) {
        int r = i >> 5, cu = i & 31;
        CP_ASYNC16(sdst + r * 512 + ((cu ^ (r & 7)) << 4), g + r * 256 + cu * 8);
    }
}
// 256 rows x 128 fp16 (256B rows), src rows stride W_DIM
__device__ __forceinline__ void cp_tileW2(uint32_t sdst, const __half* g) {
    for (int i = threadIdx.x; i < 4096; i += NTHREADS) {
        int r = i >> 4, cu = i & 15;
        CP_ASYNC16(sdst + r * 256 + ((cu ^ (r & 7)) << 4), g + (size_t)r * W_DIM + cu * 8);
    }
}

// ---------------- main fused kernel ----------------
__global__ void __launch_bounds__(NTHREADS, 1)
planar_mma_kernel(const float* __restrict__ z,
                  const float* __restrict__ b1,
                  float* __restrict__ dz_out,
                  float* __restrict__ dlog_out) {
    extern __shared__ char smem[];
    const uint32_t sb = smem_u32(smem);
    float* sTr = reinterpret_cast<float*>(smem + TR_OFF);

    const int tid  = threadIdx.x;
    const int wid  = tid >> 5;
    const int lane = tid & 31;
    const int mg   = wid >> 3;     // 0..1 : rows 32*mg .. +31
    const int ng   = wid & 7;      // GEMM1: 16 cols; GEMM2: 32 cols
    const int row0 = blockIdx.x * MTILE;

    if (tid < MTILE) sTr[tid] = 0.0f;

    // prologue: weights via cp.async; z fp32 -> fp16 converted inline
    cp_tile512(sb + W1_S, g_w1s, 128);
    cp_tileW2(sb + W2_S, g_w2s);
    CP_COMMIT();
    {
        const float4* zg = reinterpret_cast<const float4*>(z + (size_t)row0 * D_DIM);
        for (int i = tid; i < MTILE * 32; i += NTHREADS) {
            int r = i >> 5, cu = i & 31;
            float4 a = zg[r * 64 + cu * 2];
            float4 b = zg[r * 64 + cu * 2 + 1];
            float v[8] = {a.x, a.y, a.z, a.w, b.x, b.y, b.z, b.w};
            PackH8 o;
            #pragma unroll
            for (int q = 0; q < 8; q++) o.h[q] = __float2half_rn(v[q]);
            const uint32_t da = sb + Z_S + r * 512 + ((cu ^ (r & 7)) << 4);
            asm volatile("st.shared.v4.b32 [%0], {%1,%2,%3,%4};"
                :: "r"(da), "r"(o.u.x), "r"(o.u.y), "r"(o.u.z), "r"(o.u.w) : "memory");
        }
    }
    CP_WAIT0();
    __syncthreads();

    // per-lane fragment addressing (XOR swizzle; swz == lane&7 for all reads)
    const int lr    = lane & 15;
    const int kodd  = lane >> 4;
    const int brow  = (lane & 7) + ((lane >> 4) << 3);
    const int koddb = (lane >> 3) & 1;
    const int swz   = lane & 7;

    const uint32_t zbase  = sb + Z_S  + (mg * 32 + lr) * 512;
    const uint32_t w1base = sb + W1_S + (ng * 16 + brow) * 512;
    const uint32_t hbase  = sb + H_S  + (mg * 32 + lr) * 256;
    const uint32_t w2base = sb + W2_S + (ng * 32 + brow) * 256;

    float dz[2][4][4];
    #pragma unroll
    for (int a = 0; a < 2; a++)
        #pragma unroll
        for (int b = 0; b < 4; b++)
            #pragma unroll
            for (int c = 0; c < 4; c++) dz[a][b][c] = 0.0f;
    float tr4[4] = {0.f, 0.f, 0.f, 0.f};

    for (int ch = 0; ch < NCHUNK; ch++) {
        const int jc = ch * CW;

        // ---------- GEMM1: pre = z @ (64*W1chunk)^T, warp m32n16 --------------
        float pre[2][2][4];
        #pragma unroll
        for (int a = 0; a < 2; a++)
            #pragma unroll
            for (int b = 0; b < 2; b++)
                #pragma unroll
                for (int c = 0; c < 4; c++) pre[a][b][c] = 0.0f;

        #pragma unroll
        for (int ks = 0; ks < 16; ks++) {
            const uint32_t offA = (uint32_t)(((ks * 2 + kodd)  ^ swz) << 4);
            const uint32_t offB = (uint32_t)(((ks * 2 + koddb) ^ swz) << 4);
            uint32_t ah0[4], ah1[4], bh[4];
            LDSM4(ah0, zbase + offA);
            LDSM4(ah1, zbase + 16 * 512 + offA);
            LDSM4(bh,  w1base + offB);
            mma_f16(pre[0][0], ah0, bh[0], bh[1]);
            mma_f16(pre[0][1], ah0, bh[2], bh[3]);
            mma_f16(pre[1][0], ah1, bh[0], bh[1]);
            mma_f16(pre[1][1], ah1, bh[2], bh[3]);
        }

        // ---------- epilogue: x = pre/64 + b1; softplus -> h; trace -----------
        #pragma unroll
        for (int mf = 0; mf < 2; mf++) {
            #pragma unroll
            for (int nf = 0; nf < 2; nf++) {
                const int j0 = jc + ng * 16 + nf * 8 + 2 * (lane & 3);
                const float b10 = __ldg(&b1[j0]),   b11 = __ldg(&b1[j0 + 1]);
                const float M0  = g_M[j0],          M1  = g_M[j0 + 1];
                const int clu = ng * 2 + nf;   // 16B-unit col index in h row
                #pragma unroll
                for (int bq = 0; bq < 2; bq++) {
                    float x0 = fmaf(pre[mf][nf][2 * bq],     WINV, b10);
                    float x1 = fmaf(pre[mf][nf][2 * bq + 1], WINV, b11);
                    float e0 = __expf(-fabsf(x0)), e1 = __expf(-fabsf(x1));
                    float sp0 = fmaxf(x0, 0.0f) + __logf(1.0f + e0);
                    float sp1 = fmaxf(x1, 0.0f) + __logf(1.0f + e1);
                    float i0 = __fdividef(1.0f, 1.0f + e0);
                    float i1 = __fdividef(1.0f, 1.0f + e1);
                    float sg0 = (x0 >= 0.0f) ? i0 : e0 * i0;
                    float sg1 = (x1 >= 0.0f) ? i1 : e1 * i1;
                    tr4[mf * 2 + bq] = fmaf(sg0, M0, tr4[mf * 2 + bq]);
                    tr4[mf * 2 + bq] = fmaf(sg1, M1, tr4[mf * 2 + bq]);
                    __half h0 = __float2half_rn(sp0);
                    __half h1 = __float2half_rn(sp1);
                    uint32_t phi = ((uint32_t)__half_as_ushort(h1) << 16) |
                                   (uint32_t)__half_as_ushort(h0);
                    const int rl = mg * 32 + mf * 16 + (lane >> 2) + 8 * bq;
                    const uint32_t ha = sb + H_S + rl * 256 +
                                        (((uint32_t)(clu ^ (rl & 7))) << 4) +
                                        (lane & 3) * 4;
                    asm volatile("st.shared.b32 [%0], %1;" :: "r"(ha), "r"(phi) : "memory");
                }
            }
        }

        // wait for W2(ch) (issued at tail of ch-1; only group in flight)
        CP_WAIT0();
        __syncthreads();   // AB: past GEMM1 (W1 free), h written, W2(ch) visible

        // issue W1(ch+1): hidden under GEMM2(ch)
        if (ch + 1 < NCHUNK) {
            cp_tile512(sb + W1_S, g_w1s + (size_t)(jc + CW) * D_DIM, 128);
            CP_COMMIT();
        }

        // ---------- GEMM2: dz += h @ (64*W2chunk), warp m32n32, K=128 ---------
        #pragma unroll
        for (int ks = 0; ks < 8; ks++) {
            const uint32_t offA = (uint32_t)(((ks * 2 + kodd)  ^ swz) << 4);
            const uint32_t offB = (uint32_t)(((ks * 2 + koddb) ^ swz) << 4);
            uint32_t ah0[4], ah1[4], bh0[4], bh1[4];
            LDSM4(ah0, hbase + offA);
            LDSM4(ah1, hbase + 16 * 256 + offA);
            LDSM4(bh0, w2base + offB);
            LDSM4(bh1, w2base + 16 * 256 + offB);
            mma_f16(dz[0][0], ah0, bh0[0], bh0[1]);
            mma_f16(dz[0][1], ah0, bh0[2], bh0[3]);
            mma_f16(dz[0][2], ah0, bh1[0], bh1[1]);
            mma_f16(dz[0][3], ah0, bh1[2], bh1[3]);
            mma_f16(dz[1][0], ah1, bh0[0], bh0[1]);
            mma_f16(dz[1][1], ah1, bh0[2], bh0[3]);
            mma_f16(dz[1][2], ah1, bh1[0], bh1[1]);
            mma_f16(dz[1][3], ah1, bh1[2], bh1[3]);
        }

        __syncthreads();   // C: all warps past GEMM2 -> W2 buffer free

        // issue W2(ch+1): in flight across chunk boundary; wait only W1(ch+1)
        if (ch + 1 < NCHUNK) {
            cp_tileW2(sb + W2_S, g_w2s + jc + CW);
            CP_COMMIT();
            CP_WAIT1();        // W1(ch+1) done; W2(ch+1) still in flight
            __syncthreads();   // D: W1(ch+1) visible
        }
    }

    // ---------------- writeout (undo weight scale) ----------------
    // warp (mg, ng): rows mg*32 + mf*16 + lane/4 (+8), cols ng*32 + nf*8 + 2*(lane&3)
    #pragma unroll
    for (int mf = 0; mf < 2; mf++) {
        const int rl = mg * 32 + mf * 16 + (lane >> 2);
        #pragma unroll
        for (int nf = 0; nf < 4; nf++) {
            const int col = ng * 32 + nf * 8 + 2 * (lane & 3);
            float2 v0 = make_float2(dz[mf][nf][0] * WINV, dz[mf][nf][1] * WINV);
            float2 v1 = make_float2(dz[mf][nf][2] * WINV, dz[mf][nf][3] * WINV);
            *reinterpret_cast<float2*>(dz_out + (size_t)(row0 + rl) * D_DIM + col) = v0;
            *reinterpret_cast<float2*>(dz_out + (size_t)(row0 + rl + 8) * D_DIM + col) = v1;
        }
    }
    #pragma unroll
    for (int i = 0; i < 4; i++) {
        const int rl = mg * 32 + (i >> 1) * 16 + (lane >> 2) + 8 * (i & 1);
        atomicAdd(&sTr[rl], tr4[i]);
    }
    __syncthreads();
    if (tid < MTILE) dlog_out[row0 + tid] = -sTr[tid];
}

// ---------------------------------------------------------------------------
extern "C" void kernel_launch(void* const* d_in, const int* in_sizes, int n_in,
                              void* d_out, int out_size) {
    const float* z  = (const float*)d_in[1];
    const float* W1 = (const float*)d_in[2];
    const float* b1 = (const float*)d_in[3];
    const float* W2 = (const float*)d_in[4];

    float* dz   = (float*)d_out;
    float* dlog = dz + (size_t)BATCH * D_DIM;

    prep_kernel<<<WCONV_BLOCKS + W_DIM, 256>>>(W1, W2);

    cudaFuncSetAttribute(planar_mma_kernel,
                         cudaFuncAttributeMaxDynamicSharedMemorySize, S_TOTAL);
    planar_mma_kernel<<<NGRID, NTHREADS, S_TOTAL>>>(z, b1, dz, dlog);
}

// round 15
// speedup vs baseline: 1.1032x; 1.1032x over previous
#include <cuda_runtime.h>
#include <cuda_fp16.h>
#include <stdint.h>
#include <math.h>

#define BATCH  65536
#define D_DIM  256
#define W_DIM  1024
#define MTILE  128
#define NTHREADS 512
#define CW     64
#define NCHUNK (W_DIM / CW)    // 16
#define WSCALE 64.0f
#define WINV   (1.0f / 64.0f)

// tail-split: 444 full tiles (128 rows) + 136 half tiles (64 rows)
#define NFULL  444
#define NHALF  136
#define NGRID  (NFULL + NHALF)            // 580
#define ROWS_FULL_TOTAL (NFULL * MTILE)   // 56832

// device scratch: weights scaled fp16 (z converted in-kernel)
__device__ __align__(16) __half g_w1s[W_DIM * D_DIM];   // W1 * 64
__device__ __align__(16) __half g_w2s[D_DIM * W_DIM];   // W2 * 64
__device__ float g_M[W_DIM];

// ---------------- SMEM layout (bytes) ----------------
// z  : [128][512B] XOR-swizzled
// W1 : 2 x [64][512B] chunk buffers (rows = W-col j)
// W2 : 2 x [256][128B] chunk buffers (64 fp16/row)
// HX : h-fragment exchange, 8 pairs x 2 halves x 8 regs, stride-33-word slots
#define Z_S    0
#define W1_S   65536
#define W1BUF  32768
#define W2_S   131072
#define W2BUF  32768
#define HX_S   196608      // (m*2+p)*1056 + (kt*4+reg)*132 + lane*4
#define TR_OFF 213504
#define S_TOTAL 214016

// ---------------- PTX helpers ----------------
__device__ __forceinline__ uint32_t smem_u32(const void* p) {
    uint32_t a;
    asm("{ .reg .u64 t; cvta.to.shared.u64 t, %1; cvt.u32.u64 %0, t; }" : "=r"(a) : "l"(p));
    return a;
}
#define CP_ASYNC16(d, s) \
    asm volatile("cp.async.cg.shared.global [%0], [%1], 16;" :: "r"(d), "l"(s))
#define CP_COMMIT() asm volatile("cp.async.commit_group;")
#define CP_WAIT0()  asm volatile("cp.async.wait_group 0;")
#define CP_WAIT1()  asm volatile("cp.async.wait_group 1;")

#define LDSM4(r, addr) \
    asm volatile("ldmatrix.sync.aligned.m8n8.x4.shared.b16 {%0,%1,%2,%3}, [%4];" \
        : "=r"((r)[0]), "=r"((r)[1]), "=r"((r)[2]), "=r"((r)[3]) : "r"(addr))

__device__ __forceinline__ void mma_f16(float* c, const uint32_t* a, uint32_t b0, uint32_t b1) {
    asm volatile(
        "mma.sync.aligned.m16n8k16.row.col.f32.f16.f16.f32 "
        "{%0,%1,%2,%3}, {%4,%5,%6,%7}, {%8,%9}, {%0,%1,%2,%3};"
        : "+f"(c[0]), "+f"(c[1]), "+f"(c[2]), "+f"(c[3])
        : "r"(a[0]), "r"(a[1]), "r"(a[2]), "r"(a[3]), "r"(b0), "r"(b1));
}

// ---------------- fused prepass: weights conv + M, ONE launch ----------------
#define WCONV_BLOCKS 256
union PackH8 { uint4 u; __half h[8]; };

__global__ void prep_kernel(const float* __restrict__ W1,
                            const float* __restrict__ W2) {
    if (blockIdx.x < WCONV_BLOCKS) {
        size_t gid = (size_t)blockIdx.x * 256 + threadIdx.x;
        const float* src;
        __half* dst;
        size_t idx;
        if (gid < 32768) { src = W1; dst = g_w1s; idx = gid; }
        else             { src = W2; dst = g_w2s; idx = gid - 32768; }
        const float4* s = reinterpret_cast<const float4*>(src);
        float4 a = s[idx * 2], b = s[idx * 2 + 1];
        float v[8] = {a.x, a.y, a.z, a.w, b.x, b.y, b.z, b.w};
        PackH8 o;
        #pragma unroll
        for (int i = 0; i < 8; i++) o.h[i] = __float2half_rn(v[i] * WSCALE);
        reinterpret_cast<uint4*>(dst)[idx] = o.u;
    } else {
        int j = blockIdx.x - WCONV_BLOCKS, i = threadIdx.x;
        float v = W1[j * D_DIM + i] * W2[(size_t)i * W_DIM + j];
        #pragma unroll
        for (int o = 16; o > 0; o >>= 1) v += __shfl_down_sync(0xffffffffu, v, o);
        __shared__ float red[8];
        if ((i & 31) == 0) red[i >> 5] = v;
        __syncthreads();
        if (i < 8) {
            float s = red[i];
            #pragma unroll
            for (int o = 4; o > 0; o >>= 1) s += __shfl_down_sync(0xffu, s, o);
            if (i == 0) g_M[j] = s;
        }
    }
}

// ---------------- copy helpers (cp.async, swizzled dst) ----------------------
// W1 chunk: 64 rows x 256 fp16 (512B rows) -> buffer
__device__ __forceinline__ void cp_w1(uint32_t sdst, int jc) {
    for (int i = threadIdx.x; i < 2048; i += NTHREADS) {
        int r = i >> 5, cu = i & 31;
        CP_ASYNC16(sdst + r * 512 + ((cu ^ (r & 7)) << 4),
                   g_w1s + (size_t)(jc + r) * 256 + cu * 8);
    }
}
// W2 chunk: 256 rows x 64 fp16 (128B rows), src rows stride W_DIM
__device__ __forceinline__ void cp_w2(uint32_t sdst, int jc) {
    for (int i = threadIdx.x; i < 2048; i += NTHREADS) {
        int r = i >> 3, cu = i & 7;
        CP_ASYNC16(sdst + r * 128 + ((cu ^ (r & 7)) << 4),
                   g_w2s + (size_t)r * W_DIM + jc + cu * 8);
    }
}

// ---------------- main fused kernel ----------------
__global__ void __launch_bounds__(NTHREADS, 1)
planar_mma_kernel(const float* __restrict__ z,
                  const float* __restrict__ b1,
                  float* __restrict__ dz_out,
                  float* __restrict__ dlog_out) {
    extern __shared__ char smem[];
    const uint32_t sb = smem_u32(smem);
    float* sTr = reinterpret_cast<float*>(smem + TR_OFF);

    const int tid  = threadIdx.x;
    const int wid  = tid >> 5;
    const int lane = tid & 31;
    const int m    = wid >> 1;     // 0..7 : rows 16*m .. +15
    const int p    = wid & 1;      // n-half

    // tail-split tile mapping
    const int bid = blockIdx.x;
    int row0, ra;
    if (bid < NFULL) { row0 = bid * MTILE;                          ra = MTILE; }
    else             { row0 = ROWS_FULL_TOTAL + (bid - NFULL) * 64; ra = 64; }
    const bool act = (m * 16) < ra;   // warp-uniform (pair-uniform)

    if (tid < MTILE) sTr[tid] = 0.0f;

    // prologue: weight chunks 0 and 1 into both buffers; z converted inline
    cp_w1(sb + W1_S, 0);
    cp_w2(sb + W2_S, 0);
    CP_COMMIT();
    cp_w1(sb + W1_S + W1BUF, CW);
    cp_w2(sb + W2_S + W2BUF, CW);
    CP_COMMIT();
    {
        const float4* zg = reinterpret_cast<const float4*>(z + (size_t)row0 * D_DIM);
        const int total = ra * 32;
        for (int i = tid; i < total; i += NTHREADS) {
            int r = i >> 5, cu = i & 31;
            float4 a = zg[r * 64 + cu * 2];
            float4 b = zg[r * 64 + cu * 2 + 1];
            float v[8] = {a.x, a.y, a.z, a.w, b.x, b.y, b.z, b.w};
            PackH8 o;
            #pragma unroll
            for (int q = 0; q < 8; q++) o.h[q] = __float2half_rn(v[q]);
            const uint32_t da = sb + Z_S + r * 512 + ((cu ^ (r & 7)) << 4);
            asm volatile("st.shared.v4.b32 [%0], {%1,%2,%3,%4};"
                :: "r"(da), "r"(o.u.x), "r"(o.u.y), "r"(o.u.z), "r"(o.u.w) : "memory");
        }
    }
    CP_WAIT1();       // chunk-0 weights done (chunk-1 still in flight)
    __syncthreads();

    // per-lane fragment addressing (XOR swizzle; swz == lane&7)
    const int lr    = lane & 15;
    const int kodd  = lane >> 4;
    const int brow  = (lane & 7) + ((lane >> 4) << 3);
    const int koddb = (lane >> 3) & 1;
    const int swz   = lane & 7;

    const uint32_t zbase  = sb + Z_S + (m * 16 + lr) * 512;
    const uint32_t hx_own = sb + HX_S + (m * 2 + p) * 1056 + lane * 4;
    const uint32_t hx_par = sb + HX_S + (m * 2 + (p ^ 1)) * 1056 + lane * 4;
    const int pairBar = 1 + m;    // named barrier ids 1..8

    float dz[16][4];
    #pragma unroll
    for (int a = 0; a < 16; a++)
        #pragma unroll
        for (int c = 0; c < 4; c++) dz[a][c] = 0.0f;
    float tr2[2] = {0.f, 0.f};

    for (int ch = 0; ch < NCHUNK; ch++) {
        const int jc  = ch * CW;
        const int buf = ch & 1;
        const uint32_t w1b = sb + W1_S + buf * W1BUF;
        const uint32_t w2b = sb + W2_S + buf * W2BUF;

        if (act) {
            // ---- GEMM1: pre(m16 x n32) = z @ (64*W1)^T, own n-half ----------
            float pre[4][4];
            #pragma unroll
            for (int a = 0; a < 4; a++)
                #pragma unroll
                for (int c = 0; c < 4; c++) pre[a][c] = 0.0f;

            const uint32_t w1r0 = w1b + (p * 32 + brow) * 512;
            const uint32_t w1r1 = w1b + (p * 32 + 16 + brow) * 512;
            #pragma unroll
            for (int ks = 0; ks < 16; ks++) {
                const uint32_t offA = (uint32_t)(((ks * 2 + kodd)  ^ swz) << 4);
                const uint32_t offB = (uint32_t)(((ks * 2 + koddb) ^ swz) << 4);
                uint32_t av[4], b0[4], b1t[4];
                LDSM4(av, zbase + offA);
                LDSM4(b0,  w1r0 + offB);
                LDSM4(b1t, w1r1 + offB);
                mma_f16(pre[0], av, b0[0],  b0[1]);
                mma_f16(pre[1], av, b0[2],  b0[3]);
                mma_f16(pre[2], av, b1t[0], b1t[1]);
                mma_f16(pre[3], av, b1t[2], b1t[3]);
            }

            // ---- epilogue in registers: softplus -> A-fragments; trace ------
            uint32_t aown[2][4];
            #pragma unroll
            for (int nf = 0; nf < 4; nf++) {
                const int j0 = jc + p * 32 + nf * 8 + 2 * (lane & 3);
                const float b10 = __ldg(&b1[j0]), b11 = __ldg(&b1[j0 + 1]);
                const float M0 = g_M[j0], M1 = g_M[j0 + 1];
                float x0 = fmaf(pre[nf][0], WINV, b10);
                float x1 = fmaf(pre[nf][1], WINV, b11);
                float x2 = fmaf(pre[nf][2], WINV, b10);
                float x3 = fmaf(pre[nf][3], WINV, b11);
                float e0 = __expf(-fabsf(x0)), e1 = __expf(-fabsf(x1));
                float e2 = __expf(-fabsf(x2)), e3 = __expf(-fabsf(x3));
                float sp0 = fmaxf(x0, 0.f) + __logf(1.f + e0);
                float sp1 = fmaxf(x1, 0.f) + __logf(1.f + e1);
                float sp2 = fmaxf(x2, 0.f) + __logf(1.f + e2);
                float sp3 = fmaxf(x3, 0.f) + __logf(1.f + e3);
                float i0 = __fdividef(1.f, 1.f + e0), i1 = __fdividef(1.f, 1.f + e1);
                float i2 = __fdividef(1.f, 1.f + e2), i3 = __fdividef(1.f, 1.f + e3);
                float sg0 = (x0 >= 0.f) ? i0 : e0 * i0;
                float sg1 = (x1 >= 0.f) ? i1 : e1 * i1;
                float sg2 = (x2 >= 0.f) ? i2 : e2 * i2;
                float sg3 = (x3 >= 0.f) ? i3 : e3 * i3;
                tr2[0] = fmaf(sg0, M0, fmaf(sg1, M1, tr2[0]));
                tr2[1] = fmaf(sg2, M0, fmaf(sg3, M1, tr2[1]));
                __half h0 = __float2half_rn(sp0), h1 = __float2half_rn(sp1);
                __half h2 = __float2half_rn(sp2), h3 = __float2half_rn(sp3);
                const int kt = nf >> 1, half = nf & 1;
                aown[kt][2 * half]     = ((uint32_t)__half_as_ushort(h1) << 16) |
                                          (uint32_t)__half_as_ushort(h0);
                aown[kt][2 * half + 1] = ((uint32_t)__half_as_ushort(h3) << 16) |
                                          (uint32_t)__half_as_ushort(h2);
            }

            // export own h-fragments to partner (conflict-free stride-33 slots)
            #pragma unroll
            for (int kt = 0; kt < 2; kt++)
                #pragma unroll
                for (int r = 0; r < 4; r++)
                    asm volatile("st.shared.b32 [%0], %1;"
                        :: "r"(hx_own + (kt * 4 + r) * 132), "r"(aown[kt][r]) : "memory");

            // ---- GEMM2 own k-half (ksteps 2p, 2p+1), A from registers -------
            #pragma unroll
            for (int kt = 0; kt < 2; kt++) {
                const int k2 = 2 * p + kt;
                const uint32_t offB2 = (uint32_t)(((k2 * 2 + koddb) ^ swz) << 4);
                #pragma unroll
                for (int t = 0; t < 8; t++) {
                    uint32_t bh[4];
                    LDSM4(bh, w2b + (p * 128 + t * 16 + brow) * 128 + offB2);
                    mma_f16(dz[2 * t],     aown[kt], bh[0], bh[1]);
                    mma_f16(dz[2 * t + 1], aown[kt], bh[2], bh[3]);
                }
            }

            asm volatile("bar.sync %0, 64;" :: "r"(pairBar) : "memory");

            // ---- GEMM2 partner k-half, A from exchange buffer ---------------
            #pragma unroll
            for (int kt = 0; kt < 2; kt++) {
                const int k2 = 2 * (p ^ 1) + kt;
                uint32_t ap[4];
                #pragma unroll
                for (int r = 0; r < 4; r++)
                    asm volatile("ld.shared.b32 %0, [%1];"
                        : "=r"(ap[r]) : "r"(hx_par + (kt * 4 + r) * 132));
                const uint32_t offB2 = (uint32_t)(((k2 * 2 + koddb) ^ swz) << 4);
                #pragma unroll
                for (int t = 0; t < 8; t++) {
                    uint32_t bh[4];
                    LDSM4(bh, w2b + (p * 128 + t * 16 + brow) * 128 + offB2);
                    mma_f16(dz[2 * t],     ap, bh[0], bh[1]);
                    mma_f16(dz[2 * t + 1], ap, bh[2], bh[3]);
                }
            }
        }

        // ---- chunk boundary: recycle buffer, surface next chunk's weights ---
        if (ch + 1 < NCHUNK) {
            __syncthreads();                 // all warps done reading buf
            if (ch + 2 < NCHUNK) {
                cp_w1(sb + W1_S + buf * W1BUF, jc + 2 * CW);
                cp_w2(sb + W2_S + buf * W2BUF, jc + 2 * CW);
                CP_COMMIT();
                CP_WAIT1();                  // W(ch+1) complete
            } else {
                CP_WAIT0();                  // last in-flight group
            }
            __syncthreads();                 // W(ch+1) visible to all
        }
    }

    // ---------------- writeout (undo weight scale) ----------------
    if (act) {
        const int r0 = m * 16 + (lane >> 2);
        #pragma unroll
        for (int nf = 0; nf < 16; nf++) {
            const int col = p * 128 + nf * 8 + 2 * (lane & 3);
            float2 v0 = make_float2(dz[nf][0] * WINV, dz[nf][1] * WINV);
            float2 v1 = make_float2(dz[nf][2] * WINV, dz[nf][3] * WINV);
            *reinterpret_cast<float2*>(dz_out + (size_t)(row0 + r0) * D_DIM + col) = v0;
            *reinterpret_cast<float2*>(dz_out + (size_t)(row0 + r0 + 8) * D_DIM + col) = v1;
        }
        atomicAdd(&sTr[r0],     tr2[0]);
        atomicAdd(&sTr[r0 + 8], tr2[1]);
    }
    __syncthreads();
    if (tid < ra) dlog_out[row0 + tid] = -sTr[tid];
}

// ---------------------------------------------------------------------------
extern "C" void kernel_launch(void* const* d_in, const int* in_sizes, int n_in,
                              void* d_out, int out_size) {
    const float* z  = (const float*)d_in[1];
    const float* W1 = (const float*)d_in[2];
    const float* b1 = (const float*)d_in[3];
    const float* W2 = (const float*)d_in[4];

    float* dz   = (float*)d_out;
    float* dlog = dz + (size_t)BATCH * D_DIM;

    prep_kernel<<<WCONV_BLOCKS + W_DIM, 256>>>(W1, W2);

    cudaFuncSetAttribute(planar_mma_kernel,
                         cudaFuncAttributeMaxDynamicSharedMemorySize, S_TOTAL);
    planar_mma_kernel<<<NGRID, NTHREADS, S_TOTAL>>>(z, b1, dz, dlog);
}